// round 12
// baseline (speedup 1.0000x reference)
#include <cuda_runtime.h>
#include <cuda_bf16.h>
#include <cfloat>
#include <math.h>

#define VOC   32000
#define EMB   512
#define HID   1024
#define BATCH 16
#define SEQ   256
#define G4    4096
#define ROWS  4096   // B*S
#define NCTA  128

// ------------------------------- device scratch ---------------------------
__device__ float g_X[ROWS * EMB];
__device__ float g_A[ROWS * G4];
__device__ float g_h1seq[ROWS * HID];   // rows r = s*16+b
__device__ float g_h2seq[ROWS * HID];   // rows r = b*256+s
__device__ float g_h[2 * BATCH * HID];
__device__ float g_lse[ROWS];
__device__ float g_bias[2 * G4];
__device__ int   g_is64;
__device__ unsigned g_cnt = 0;
__device__ unsigned g_gen = 0;

// ------------------------------- small kernels ----------------------------
__global__ void zero_k(float* p, int n) {
    int i = blockIdx.x * 256 + threadIdx.x;
    if (i < n) p[i] = 0.f;
}

__global__ void detect_i64(const unsigned int* p) {
    __shared__ int any;
    if (threadIdx.x == 0) any = 0;
    __syncthreads();
    int loc = 0;
    for (int i = threadIdx.x; i < 2048; i += 256) loc |= (p[2 * i + 1] != 0u);
    if (loc) atomicOr(&any, 1);
    __syncthreads();
    if (threadIdx.x == 0) g_is64 = (any == 0) ? 1 : 0;
}

__global__ void combine_bias(const float* __restrict__ a1, const float* __restrict__ a2,
                             const float* __restrict__ b1, const float* __restrict__ b2) {
    int i = blockIdx.x * 256 + threadIdx.x;
    if (i < G4) { g_bias[i] = a1[i] + a2[i]; g_bias[G4 + i] = b1[i] + b2[i]; }
}

__global__ void gather_x(const void* __restrict__ inp, const float* __restrict__ emb) {
    int idx4 = blockIdx.x * 256 + threadIdx.x;        // ROWS*128
    if (idx4 >= ROWS * (EMB / 4)) return;
    int r = idx4 >> 7, e4 = idx4 & 127;
    int s = r >> 4, b = r & 15;
    int pos = b * SEQ + s;
    int tok = g_is64 ? (int)((const long long*)inp)[pos] : ((const int*)inp)[pos];
    reinterpret_cast<float4*>(g_X)[idx4] =
        reinterpret_cast<const float4*>(emb)[(size_t)tok * 128 + e4];
}

// ------------------------------- SGEMM NT (pipelined) ---------------------
// C[m][n] = sum_k A[m*K+k]*B[n*K+k] + bias[n]; 128x128 tile, 8x8/thread,
// next k-slab prefetched into registers during the FMA block.
__global__ void __launch_bounds__(256, 2) gemm_nt(
    const float* __restrict__ A, const float* __restrict__ B, float* __restrict__ C,
    int M, int N, int K, const float* __restrict__ bias)
{
    __shared__ __align__(16) float As[16][132];
    __shared__ __align__(16) float Bs[16][132];
    const int tid = threadIdx.x;
    const int n0 = blockIdx.x * 128, m0 = blockIdx.y * 128;
    const int tx = tid & 15, ty = tid >> 4;
    const int lr = tid >> 1, lk = (tid & 1) * 8;

    float acc[8][8];
#pragma unroll
    for (int i = 0; i < 8; i++)
#pragma unroll
        for (int j = 0; j < 8; j++) acc[i][j] = 0.f;

    const float* Ap = A + (size_t)(m0 + lr) * K + lk;
    const float* Bp = B + (size_t)(n0 + lr) * K + lk;

    float4 a0 = *reinterpret_cast<const float4*>(Ap);
    float4 a1 = *reinterpret_cast<const float4*>(Ap + 4);
    float4 b0 = *reinterpret_cast<const float4*>(Bp);
    float4 b1 = *reinterpret_cast<const float4*>(Bp + 4);
    As[lk+0][lr]=a0.x; As[lk+1][lr]=a0.y; As[lk+2][lr]=a0.z; As[lk+3][lr]=a0.w;
    As[lk+4][lr]=a1.x; As[lk+5][lr]=a1.y; As[lk+6][lr]=a1.z; As[lk+7][lr]=a1.w;
    Bs[lk+0][lr]=b0.x; Bs[lk+1][lr]=b0.y; Bs[lk+2][lr]=b0.z; Bs[lk+3][lr]=b0.w;
    Bs[lk+4][lr]=b1.x; Bs[lk+5][lr]=b1.y; Bs[lk+6][lr]=b1.z; Bs[lk+7][lr]=b1.w;
    __syncthreads();

    for (int k0 = 16; k0 <= K; k0 += 16) {
        bool more = (k0 < K);
        if (more) {
            a0 = *reinterpret_cast<const float4*>(Ap + k0);
            a1 = *reinterpret_cast<const float4*>(Ap + k0 + 4);
            b0 = *reinterpret_cast<const float4*>(Bp + k0);
            b1 = *reinterpret_cast<const float4*>(Bp + k0 + 4);
        }
#pragma unroll
        for (int kk = 0; kk < 16; ++kk) {
            float4 t0 = *reinterpret_cast<const float4*>(&As[kk][ty * 4]);
            float4 t1 = *reinterpret_cast<const float4*>(&As[kk][64 + ty * 4]);
            float4 u0 = *reinterpret_cast<const float4*>(&Bs[kk][tx * 4]);
            float4 u1 = *reinterpret_cast<const float4*>(&Bs[kk][64 + tx * 4]);
            float a[8] = { t0.x,t0.y,t0.z,t0.w, t1.x,t1.y,t1.z,t1.w };
            float b[8] = { u0.x,u0.y,u0.z,u0.w, u1.x,u1.y,u1.z,u1.w };
#pragma unroll
            for (int i = 0; i < 8; i++)
#pragma unroll
                for (int j = 0; j < 8; j++)
                    acc[i][j] = fmaf(a[i], b[j], acc[i][j]);
        }
        if (more) {
            __syncthreads();
            As[lk+0][lr]=a0.x; As[lk+1][lr]=a0.y; As[lk+2][lr]=a0.z; As[lk+3][lr]=a0.w;
            As[lk+4][lr]=a1.x; As[lk+5][lr]=a1.y; As[lk+6][lr]=a1.z; As[lk+7][lr]=a1.w;
            Bs[lk+0][lr]=b0.x; Bs[lk+1][lr]=b0.y; Bs[lk+2][lr]=b0.z; Bs[lk+3][lr]=b0.w;
            Bs[lk+4][lr]=b1.x; Bs[lk+5][lr]=b1.y; Bs[lk+6][lr]=b1.z; Bs[lk+7][lr]=b1.w;
            __syncthreads();
        }
    }

    float bn[8];
#pragma unroll
    for (int j = 0; j < 8; j++)
        bn[j] = bias ? bias[n0 + (j >> 2) * 64 + tx * 4 + (j & 3)] : 0.f;
#pragma unroll
    for (int i = 0; i < 8; i++) {
        int m = m0 + (i >> 2) * 64 + ty * 4 + (i & 3);
        float4 v0 = make_float4(acc[i][0]+bn[0], acc[i][1]+bn[1], acc[i][2]+bn[2], acc[i][3]+bn[3]);
        float4 v1 = make_float4(acc[i][4]+bn[4], acc[i][5]+bn[5], acc[i][6]+bn[6], acc[i][7]+bn[7]);
        *reinterpret_cast<float4*>(&C[(size_t)m * N + n0 + tx * 4]) = v0;
        *reinterpret_cast<float4*>(&C[(size_t)m * N + n0 + 64 + tx * 4]) = v1;
    }
}

// ------------------------------- grid barrier ------------------------------
__device__ __forceinline__ unsigned ld_cg_u32(const unsigned* p) {
    unsigned v;
    asm volatile("ld.global.cg.u32 %0, [%1];" : "=r"(v) : "l"(p));
    return v;
}

__device__ __forceinline__ void grid_barrier() {
    __syncthreads();
    if (threadIdx.x == 0) {
        __threadfence();
        unsigned g = ld_cg_u32(&g_gen);
        if (atomicAdd(&g_cnt, 1u) == NCTA - 1) {
            atomicExch(&g_cnt, 0u);
            __threadfence();
            atomicAdd(&g_gen, 1u);
        } else {
            while (ld_cg_u32(&g_gen) == g) __nanosleep(64);
        }
        __threadfence();
    }
    __syncthreads();
}

// ------------------------------- persistent LSTM layer --------------------
// 128 CTAs (one wave), each owns 8 hidden units for all 256 steps.
// c state lives in SMEM (CTA-private). h ping-pongs in global; staging reads
// via __ldcg (L2-coherent). Whh via __ldg -> L1-resident slice across steps.
#define H_STRIDE 1028
#define CELL_SMEM ((16 * H_STRIDE + 256 * 16 + 32 * 16 + 128) * 4)

__global__ void __launch_bounds__(256) lstm_layer(
    const float* __restrict__ pregA, const float* __restrict__ Whh,
    float* __restrict__ hbuf, float* __restrict__ seq_out,
    int stride_s, int stride_b)
{
    extern __shared__ float smem[];
    float* h_sm = smem;                       // 16 * H_STRIDE
    float* red  = smem + 16 * H_STRIDE;       // 256 * 16
    float* g_sm = red + 256 * 16;             // 32 * 16
    float* c_sm = g_sm + 32 * 16;             // 128

    const int tid = threadIdx.x, cta = blockIdx.x;
    if (tid < 128) c_sm[tid] = 0.f;

    const int ks = tid >> 5, lane = tid & 31;
    const int rg = lane >> 2, bg = lane & 3;
    const int gate = rg >> 1, jl0 = (rg & 1) * 4;
    const int grow0 = gate * HID + cta * 8 + jl0;

    const float* wp[4];
#pragma unroll
    for (int r = 0; r < 4; r++) wp[r] = Whh + (size_t)(grow0 + r) * HID + ks * 128;

    for (int s = 0; s < SEQ; s++) {
        const float* h_in  = hbuf + (s & 1) * (BATCH * HID);
        float*       h_out = hbuf + ((s + 1) & 1) * (BATCH * HID);
        const float* preg  = pregA + (size_t)s * 16 * G4;

        // stage h (L2-coherent loads; other SMs wrote it last step)
        for (int t = tid; t < BATCH * (HID / 4); t += 256) {
            int b = t >> 8, k4 = t & 255;
            float4 v = __ldcg(reinterpret_cast<const float4*>(h_in) + b * 256 + k4);
            *reinterpret_cast<float4*>(&h_sm[b * H_STRIDE + k4 * 4]) = v;
        }
        __syncthreads();

        const float* hq[4];
#pragma unroll
        for (int q = 0; q < 4; q++) hq[q] = &h_sm[(bg + 4 * q) * H_STRIDE + ks * 128];

        float acc[16];
#pragma unroll
        for (int q = 0; q < 16; q++) acc[q] = 0.f;

#pragma unroll 4
        for (int kk = 0; kk < 128; kk += 4) {
            float4 wv[4], hv[4];
#pragma unroll
            for (int r = 0; r < 4; r++)
                wv[r] = __ldg(reinterpret_cast<const float4*>(wp[r] + kk));
#pragma unroll
            for (int q = 0; q < 4; q++)
                hv[q] = *reinterpret_cast<const float4*>(hq[q] + kk);
#pragma unroll
            for (int r = 0; r < 4; r++)
#pragma unroll
                for (int q = 0; q < 4; q++) {
                    float v = acc[r * 4 + q];
                    v = fmaf(wv[r].x, hv[q].x, v);
                    v = fmaf(wv[r].y, hv[q].y, v);
                    v = fmaf(wv[r].z, hv[q].z, v);
                    v = fmaf(wv[r].w, hv[q].w, v);
                    acc[r * 4 + q] = v;
                }
        }

#pragma unroll
        for (int q = 0; q < 16; q++) red[tid * 16 + q] = acc[q];
        __syncthreads();

        if (tid < 32) {
            int trg = tid >> 2, tbg = tid & 3;
            int tgate = trg >> 1, tjl0 = (trg & 1) * 4;
#pragma unroll
            for (int rr = 0; rr < 4; rr++) {
                int grow = tgate * HID + cta * 8 + tjl0 + rr;
                int lrow = trg * 4 + rr;
#pragma unroll
                for (int bb = 0; bb < 4; bb++) {
                    int b = tbg + 4 * bb;
                    float sum = 0.f;
#pragma unroll
                    for (int p = 0; p < 8; p++) sum += red[(p * 32 + tid) * 16 + rr * 4 + bb];
                    g_sm[lrow * 16 + b] = sum + preg[b * G4 + grow];
                }
            }
        }
        __syncthreads();

        if (tid < 128) {
            int jl = tid & 7, b = tid >> 3;
            float iv = g_sm[(0  + jl) * 16 + b];
            float fv = g_sm[(8  + jl) * 16 + b];
            float gv = g_sm[(16 + jl) * 16 + b];
            float ov = g_sm[(24 + jl) * 16 + b];
            float si = 1.f / (1.f + expf(-iv));
            float sf = 1.f / (1.f + expf(-fv));
            float so = 1.f / (1.f + expf(-ov));
            float cn = sf * c_sm[tid] + si * tanhf(gv);
            float hn = so * tanhf(cn);
            c_sm[tid] = cn;
            h_out[b * HID + cta * 8 + jl] = hn;
            seq_out[(size_t)s * stride_s + (size_t)b * stride_b + cta * 8 + jl] = hn;
        }
        grid_barrier();
    }
}

// ------------------------------- log-softmax ------------------------------
__device__ __forceinline__ float fast_exp_neg(float x) {   // x <= 0
    x = fmaxf(x, -87.0f);
    float t = x * 1.4426950408889634f;
    float fl = floorf(t);
    float r = t - fl;
    float p = 1.5403530393381609e-4f;
    p = fmaf(p, r, 1.3333558146428443e-3f);
    p = fmaf(p, r, 9.6181291076284772e-3f);
    p = fmaf(p, r, 5.5504108664821580e-2f);
    p = fmaf(p, r, 2.4022650695910072e-1f);
    p = fmaf(p, r, 6.9314718055994531e-1f);
    p = fmaf(p, r, 1.0f);
    return p * __int_as_float(((int)fl + 127) << 23);
}

__global__ void lse_kernel(const float* __restrict__ logits, float* __restrict__ lse) {
    __shared__ float sm[256], ss[256];
    const int row = blockIdx.x, tid = threadIdx.x;
    const float4* base = reinterpret_cast<const float4*>(logits + (size_t)row * VOC);
    float m = -FLT_MAX, s = 0.f;
    for (int i = tid; i < VOC / 4; i += 256) {
        float4 v = base[i];
        float xs[4] = { v.x, v.y, v.z, v.w };
#pragma unroll
        for (int q = 0; q < 4; q++) {
            float x = xs[q];
            if (x > m) { s = s * fast_exp_neg(m - x) + 1.f; m = x; }
            else       { s += fast_exp_neg(x - m); }
        }
    }
    sm[tid] = m; ss[tid] = s;
    __syncthreads();
    for (int off = 128; off; off >>= 1) {
        if (tid < off) {
            float m1 = sm[tid], s1 = ss[tid], m2 = sm[tid + off], s2 = ss[tid + off];
            float mm = fmaxf(m1, m2);
            ss[tid] = s1 * fast_exp_neg(m1 - mm) + s2 * fast_exp_neg(m2 - mm);
            sm[tid] = mm;
        }
        __syncthreads();
    }
    if (tid == 0) lse[row] = sm[0] + logf(ss[0]);
}

__global__ void sub_kernel(float* __restrict__ out, const float* __restrict__ lse) {
    int idx4 = blockIdx.x * 256 + threadIdx.x;   // ROWS*(VOC/4)
    int row = idx4 / (VOC / 4);
    float l = lse[row];
    float4* p = reinterpret_cast<float4*>(out) + idx4;
    float4 v = *p;
    v.x -= l; v.y -= l; v.z -= l; v.w -= l;
    *p = v;
}

// ------------------------------- launcher ---------------------------------
extern "C" void kernel_launch(void* const* d_in, const int* in_sizes, int n_in,
                              void* d_out, int out_size) {
    (void)in_sizes; (void)n_in; (void)out_size;
    const void*  inp   = d_in[0];
    const float* emb   = (const float*)d_in[1];
    const float* W_ih1 = (const float*)d_in[2];
    const float* W_hh1 = (const float*)d_in[3];
    const float* b_ih1 = (const float*)d_in[4];
    const float* b_hh1 = (const float*)d_in[5];
    const float* W_ih2 = (const float*)d_in[6];
    const float* W_hh2 = (const float*)d_in[7];
    const float* b_ih2 = (const float*)d_in[8];
    const float* b_hh2 = (const float*)d_in[9];
    const float* W_log = (const float*)d_in[10];
    const float* b_log = (const float*)d_in[11];
    float* out = (float*)d_out;

    static bool attr_set = false;
    if (!attr_set) {
        cudaFuncSetAttribute(lstm_layer, cudaFuncAttributeMaxDynamicSharedMemorySize, CELL_SMEM);
        attr_set = true;
    }

    float *X, *A, *h1s, *h2s, *h, *lse, *bias;
    cudaGetSymbolAddress((void**)&X,    g_X);
    cudaGetSymbolAddress((void**)&A,    g_A);
    cudaGetSymbolAddress((void**)&h1s,  g_h1seq);
    cudaGetSymbolAddress((void**)&h2s,  g_h2seq);
    cudaGetSymbolAddress((void**)&h,    g_h);
    cudaGetSymbolAddress((void**)&lse,  g_lse);
    cudaGetSymbolAddress((void**)&bias, g_bias);

    detect_i64<<<1, 256>>>((const unsigned int*)inp);
    combine_bias<<<16, 256>>>(b_ih1, b_hh1, b_ih2, b_hh2);
    gather_x<<<2048, 256>>>(inp, emb);

    // A1 = X @ W_ih1^T + (b_ih1 + b_hh1)
    gemm_nt<<<dim3(32, 32), 256>>>(X, W_ih1, A, ROWS, G4, EMB, bias);

    // layer 1 recurrence (persistent, seq layout rows r = s*16+b)
    zero_k<<<64, 256>>>(h, BATCH * HID);
    lstm_layer<<<NCTA, 256, CELL_SMEM>>>(A, W_hh1, h, h1s, 16 * HID, HID);

    // A2 = H1 @ W_ih2^T + (b_ih2 + b_hh2)
    gemm_nt<<<dim3(32, 32), 256>>>(h1s, W_ih2, A, ROWS, G4, HID, bias + G4);

    // layer 2 recurrence (persistent, writes [B,S,H] layout)
    zero_k<<<64, 256>>>(h, BATCH * HID);
    lstm_layer<<<NCTA, 256, CELL_SMEM>>>(A, W_hh2, h, h2s, HID, SEQ * HID);

    // logits = H2 @ W_log^T + b_log
    gemm_nt<<<dim3(250, 32), 256>>>(h2s, W_log, out, ROWS, VOC, HID, b_log);

    // log_softmax
    lse_kernel<<<ROWS, 256>>>(out, lse);
    sub_kernel<<<ROWS * (VOC / 4) / 256, 256>>>(out, lse);
}

// round 13
// speedup vs baseline: 1.1446x; 1.1446x over previous
#include <cuda_runtime.h>
#include <cuda_bf16.h>
#include <cfloat>
#include <math.h>

#define VOC   32000
#define EMB   512
#define HID   1024
#define BATCH 16
#define SEQ   256
#define G4    4096
#define ROWS  4096   // B*S
#define NCTA  128

// ------------------------------- device scratch ---------------------------
__device__ float g_X[ROWS * EMB];
__device__ float g_A[ROWS * G4];
__device__ float g_h1seq[ROWS * HID];   // rows r = s*16+b
__device__ float g_h2seq[ROWS * HID];   // rows r = b*256+s
__device__ float g_h[2 * BATCH * HID];
__device__ float g_lse[ROWS];
__device__ float g_bias[2 * G4];
__device__ int   g_is64;
__device__ unsigned g_cnt = 0;
__device__ unsigned g_gen = 0;

// ------------------------------- f32x2 helpers -----------------------------
__device__ __forceinline__ void ffma2(unsigned long long& d,
                                      unsigned long long a,
                                      unsigned long long b) {
    asm("fma.rn.f32x2 %0, %1, %2, %0;" : "+l"(d) : "l"(a), "l"(b));
}
__device__ __forceinline__ unsigned long long pack2(float x, float y) {
    unsigned long long d;
    asm("mov.b64 %0, {%1, %2};" : "=l"(d) : "f"(x), "f"(y));
    return d;
}
__device__ __forceinline__ float2 unpack2(unsigned long long d) {
    float2 r;
    asm("mov.b64 {%0, %1}, %2;" : "=f"(r.x), "=f"(r.y) : "l"(d));
    return r;
}

// ------------------------------- small kernels ----------------------------
__global__ void zero_k(float* p, int n) {
    int i = blockIdx.x * 256 + threadIdx.x;
    if (i < n) p[i] = 0.f;
}

__global__ void detect_i64(const unsigned int* p) {
    __shared__ int any;
    if (threadIdx.x == 0) any = 0;
    __syncthreads();
    int loc = 0;
    for (int i = threadIdx.x; i < 2048; i += 256) loc |= (p[2 * i + 1] != 0u);
    if (loc) atomicOr(&any, 1);
    __syncthreads();
    if (threadIdx.x == 0) g_is64 = (any == 0) ? 1 : 0;
}

__global__ void combine_bias(const float* __restrict__ a1, const float* __restrict__ a2,
                             const float* __restrict__ b1, const float* __restrict__ b2) {
    int i = blockIdx.x * 256 + threadIdx.x;
    if (i < G4) { g_bias[i] = a1[i] + a2[i]; g_bias[G4 + i] = b1[i] + b2[i]; }
}

__global__ void gather_x(const void* __restrict__ inp, const float* __restrict__ emb) {
    int idx4 = blockIdx.x * 256 + threadIdx.x;        // ROWS*128
    if (idx4 >= ROWS * (EMB / 4)) return;
    int r = idx4 >> 7, e4 = idx4 & 127;
    int s = r >> 4, b = r & 15;
    int pos = b * SEQ + s;
    int tok = g_is64 ? (int)((const long long*)inp)[pos] : ((const int*)inp)[pos];
    reinterpret_cast<float4*>(g_X)[idx4] =
        reinterpret_cast<const float4*>(emb)[(size_t)tok * 128 + e4];
}

// ------------------------------- SGEMM NT (f32x2, pipelined) ---------------
// C[m][n] = sum_k A[m*K+k]*B[n*K+k] + bias[n]; 128x128 tile, 8x8/thread.
__global__ void __launch_bounds__(256, 2) gemm_nt(
    const float* __restrict__ A, const float* __restrict__ B, float* __restrict__ C,
    int M, int N, int K, const float* __restrict__ bias)
{
    __shared__ __align__(16) float As[16][132];
    __shared__ __align__(16) float Bs[16][132];
    const int tid = threadIdx.x;
    const int n0 = blockIdx.x * 128, m0 = blockIdx.y * 128;
    const int tx = tid & 15, ty = tid >> 4;
    const int lr = tid >> 1, lk = (tid & 1) * 8;

    unsigned long long acc2[8][4];
#pragma unroll
    for (int i = 0; i < 8; i++)
#pragma unroll
        for (int j = 0; j < 4; j++) acc2[i][j] = 0ull;

    const float* Ap = A + (size_t)(m0 + lr) * K + lk;
    const float* Bp = B + (size_t)(n0 + lr) * K + lk;

    float4 a0 = *reinterpret_cast<const float4*>(Ap);
    float4 a1 = *reinterpret_cast<const float4*>(Ap + 4);
    float4 b0 = *reinterpret_cast<const float4*>(Bp);
    float4 b1 = *reinterpret_cast<const float4*>(Bp + 4);
    As[lk+0][lr]=a0.x; As[lk+1][lr]=a0.y; As[lk+2][lr]=a0.z; As[lk+3][lr]=a0.w;
    As[lk+4][lr]=a1.x; As[lk+5][lr]=a1.y; As[lk+6][lr]=a1.z; As[lk+7][lr]=a1.w;
    Bs[lk+0][lr]=b0.x; Bs[lk+1][lr]=b0.y; Bs[lk+2][lr]=b0.z; Bs[lk+3][lr]=b0.w;
    Bs[lk+4][lr]=b1.x; Bs[lk+5][lr]=b1.y; Bs[lk+6][lr]=b1.z; Bs[lk+7][lr]=b1.w;
    __syncthreads();

    for (int k0 = 16; k0 <= K; k0 += 16) {
        bool more = (k0 < K);
        if (more) {
            a0 = *reinterpret_cast<const float4*>(Ap + k0);
            a1 = *reinterpret_cast<const float4*>(Ap + k0 + 4);
            b0 = *reinterpret_cast<const float4*>(Bp + k0);
            b1 = *reinterpret_cast<const float4*>(Bp + k0 + 4);
        }
#pragma unroll
        for (int kk = 0; kk < 16; ++kk) {
            float4 t0 = *reinterpret_cast<const float4*>(&As[kk][ty * 4]);
            float4 t1 = *reinterpret_cast<const float4*>(&As[kk][64 + ty * 4]);
            ulonglong2 u0 = *reinterpret_cast<const ulonglong2*>(&Bs[kk][tx * 4]);
            ulonglong2 u1 = *reinterpret_cast<const ulonglong2*>(&Bs[kk][64 + tx * 4]);
            unsigned long long bp[4] = { u0.x, u0.y, u1.x, u1.y };
            float a[8] = { t0.x,t0.y,t0.z,t0.w, t1.x,t1.y,t1.z,t1.w };
#pragma unroll
            for (int i = 0; i < 8; i++) {
                unsigned long long ai = pack2(a[i], a[i]);
#pragma unroll
                for (int j = 0; j < 4; j++) ffma2(acc2[i][j], ai, bp[j]);
            }
        }
        if (more) {
            __syncthreads();
            As[lk+0][lr]=a0.x; As[lk+1][lr]=a0.y; As[lk+2][lr]=a0.z; As[lk+3][lr]=a0.w;
            As[lk+4][lr]=a1.x; As[lk+5][lr]=a1.y; As[lk+6][lr]=a1.z; As[lk+7][lr]=a1.w;
            Bs[lk+0][lr]=b0.x; Bs[lk+1][lr]=b0.y; Bs[lk+2][lr]=b0.z; Bs[lk+3][lr]=b0.w;
            Bs[lk+4][lr]=b1.x; Bs[lk+5][lr]=b1.y; Bs[lk+6][lr]=b1.z; Bs[lk+7][lr]=b1.w;
            __syncthreads();
        }
    }

    float bn[8];
#pragma unroll
    for (int j = 0; j < 8; j++)
        bn[j] = bias ? bias[n0 + (j >> 2) * 64 + tx * 4 + (j & 3)] : 0.f;
#pragma unroll
    for (int i = 0; i < 8; i++) {
        int m = m0 + (i >> 2) * 64 + ty * 4 + (i & 3);
        float2 p0 = unpack2(acc2[i][0]), p1 = unpack2(acc2[i][1]);
        float2 p2 = unpack2(acc2[i][2]), p3 = unpack2(acc2[i][3]);
        float4 v0 = make_float4(p0.x+bn[0], p0.y+bn[1], p1.x+bn[2], p1.y+bn[3]);
        float4 v1 = make_float4(p2.x+bn[4], p2.y+bn[5], p3.x+bn[6], p3.y+bn[7]);
        *reinterpret_cast<float4*>(&C[(size_t)m * N + n0 + tx * 4]) = v0;
        *reinterpret_cast<float4*>(&C[(size_t)m * N + n0 + 64 + tx * 4]) = v1;
    }
}

// ------------------------------- grid barrier ------------------------------
__device__ __forceinline__ unsigned ld_acq(const unsigned* p) {
    unsigned v;
    asm volatile("ld.global.acquire.gpu.u32 %0, [%1];" : "=r"(v) : "l"(p));
    return v;
}

// ------------------------------- persistent LSTM layer --------------------
// 128 CTAs (one wave), each owns 8 hidden units for all 256 steps.
#define H_STRIDE 1028
#define CELL_SMEM ((16 * H_STRIDE + 256 * 16 + 32 * 16 + 128) * 4)

__global__ void __launch_bounds__(256) lstm_layer(
    const float* __restrict__ pregA, const float* __restrict__ Whh,
    float* __restrict__ hbuf, float* __restrict__ seq_out,
    int stride_s, int stride_b)
{
    extern __shared__ float smem[];
    float* h_sm = smem;                       // 16 * H_STRIDE
    float* red  = smem + 16 * H_STRIDE;       // 256 * 16
    float* g_sm = red + 256 * 16;             // 32 * 16
    float* c_sm = g_sm + 32 * 16;             // 128

    const int tid = threadIdx.x, cta = blockIdx.x;
    if (tid < 128) c_sm[tid] = 0.f;

    unsigned gb_target = 0;
    if (tid == 0) gb_target = ld_acq(&g_gen);

    const int ks = tid >> 5, lane = tid & 31;
    const int rg = lane >> 2, bg = lane & 3;
    const int gate = rg >> 1, jl0 = (rg & 1) * 4;
    const int grow0 = gate * HID + cta * 8 + jl0;

    const ulonglong2* wpp[4];
#pragma unroll
    for (int r = 0; r < 4; r++)
        wpp[r] = reinterpret_cast<const ulonglong2*>(
            Whh + (size_t)(grow0 + r) * HID + ks * 128);

    // reduce-phase geometry (tid < 128): 4 outputs per thread
    const int lrow = (tid & 127) >> 2, tbg = tid & 3;
    const int trg2 = lrow >> 2, rr2 = lrow & 3;
    const int tsrc = trg2 * 4 + tbg;
    const int grow_r = (trg2 >> 1) * HID + cta * 8 + (trg2 & 1) * 4 + rr2;

    for (int s = 0; s < SEQ; s++) {
        const float* h_in  = hbuf + (s & 1) * (BATCH * HID);
        float*       h_out = hbuf + ((s + 1) & 1) * (BATCH * HID);
        const float* preg  = pregA + (size_t)s * 16 * G4;

        // prefetch this step's gate pre-activations (DRAM first-touch)
        float pv[4] = {0.f, 0.f, 0.f, 0.f};
        if (tid < 128) {
#pragma unroll
            for (int bb = 0; bb < 4; bb++)
                pv[bb] = __ldcg(&preg[(size_t)(tbg + 4 * bb) * G4 + grow_r]);
        }

        // stage h (L2-coherent loads)
        for (int t = tid; t < BATCH * (HID / 4); t += 256) {
            int b = t >> 8, k4 = t & 255;
            float4 v = __ldcg(reinterpret_cast<const float4*>(h_in) + b * 256 + k4);
            *reinterpret_cast<float4*>(&h_sm[b * H_STRIDE + k4 * 4]) = v;
        }
        __syncthreads();

        const ulonglong2* hq[4];
#pragma unroll
        for (int q = 0; q < 4; q++)
            hq[q] = reinterpret_cast<const ulonglong2*>(
                &h_sm[(bg + 4 * q) * H_STRIDE + ks * 128]);

        unsigned long long acc2[16];
#pragma unroll
        for (int q = 0; q < 16; q++) acc2[q] = 0ull;

#pragma unroll 4
        for (int kk = 0; kk < 32; kk++) {   // 32 x (4 k-values)
            ulonglong2 wv[4], hv[4];
#pragma unroll
            for (int r = 0; r < 4; r++) wv[r] = wpp[r][kk];
#pragma unroll
            for (int q = 0; q < 4; q++) hv[q] = hq[q][kk];
#pragma unroll
            for (int r = 0; r < 4; r++)
#pragma unroll
                for (int q = 0; q < 4; q++) {
                    ffma2(acc2[r * 4 + q], wv[r].x, hv[q].x);
                    ffma2(acc2[r * 4 + q], wv[r].y, hv[q].y);
                }
        }

#pragma unroll
        for (int q = 0; q < 16; q++) {
            float2 p = unpack2(acc2[q]);
            red[tid * 16 + q] = p.x + p.y;
        }
        __syncthreads();

        if (tid < 128) {
#pragma unroll
            for (int bb = 0; bb < 4; bb++) {
                float sum = pv[bb];
#pragma unroll
                for (int p = 0; p < 8; p++)
                    sum += red[(p * 32 + tsrc) * 16 + rr2 * 4 + bb];
                g_sm[lrow * 16 + (tbg + 4 * bb)] = sum;
            }
        }
        __syncthreads();

        if (tid < 128) {
            int jl = tid & 7, b = tid >> 3;
            float iv = g_sm[(0  + jl) * 16 + b];
            float fv = g_sm[(8  + jl) * 16 + b];
            float gv = g_sm[(16 + jl) * 16 + b];
            float ov = g_sm[(24 + jl) * 16 + b];
            float si = 1.f / (1.f + expf(-iv));
            float sf = 1.f / (1.f + expf(-fv));
            float so = 1.f / (1.f + expf(-ov));
            float cn = sf * c_sm[tid] + si * tanhf(gv);
            float hn = so * tanhf(cn);
            c_sm[tid] = cn;
            h_out[b * HID + cta * 8 + jl] = hn;
            seq_out[(size_t)s * stride_s + (size_t)b * stride_b + cta * 8 + jl] = hn;
        }

        // grid barrier (monotonic phase target)
        __syncthreads();
        if (tid == 0) {
            __threadfence();
            gb_target += 1;
            if (atomicAdd(&g_cnt, 1u) == NCTA - 1) {
                atomicExch(&g_cnt, 0u);
                __threadfence();
                atomicAdd(&g_gen, 1u);
            } else {
                while ((int)(ld_acq(&g_gen) - gb_target) < 0) __nanosleep(32);
            }
        }
        __syncthreads();
    }
}

// ------------------------------- log-softmax ------------------------------
__device__ __forceinline__ float fast_exp_neg(float x) {   // x <= 0
    x = fmaxf(x, -87.0f);
    float t = x * 1.4426950408889634f;
    float fl = floorf(t);
    float r = t - fl;
    float p = 1.5403530393381609e-4f;
    p = fmaf(p, r, 1.3333558146428443e-3f);
    p = fmaf(p, r, 9.6181291076284772e-3f);
    p = fmaf(p, r, 5.5504108664821580e-2f);
    p = fmaf(p, r, 2.4022650695910072e-1f);
    p = fmaf(p, r, 6.9314718055994531e-1f);
    p = fmaf(p, r, 1.0f);
    return p * __int_as_float(((int)fl + 127) << 23);
}

__global__ void lse_kernel(const float* __restrict__ logits, float* __restrict__ lse) {
    __shared__ float sm[256], ss[256];
    const int row = blockIdx.x, tid = threadIdx.x;
    const float4* base = reinterpret_cast<const float4*>(logits + (size_t)row * VOC);
    float m = -FLT_MAX, s = 0.f;
    for (int i = tid; i < VOC / 4; i += 256) {
        float4 v = base[i];
        float xs[4] = { v.x, v.y, v.z, v.w };
#pragma unroll
        for (int q = 0; q < 4; q++) {
            float x = xs[q];
            if (x > m) { s = s * fast_exp_neg(m - x) + 1.f; m = x; }
            else       { s += fast_exp_neg(x - m); }
        }
    }
    sm[tid] = m; ss[tid] = s;
    __syncthreads();
    for (int off = 128; off; off >>= 1) {
        if (tid < off) {
            float m1 = sm[tid], s1 = ss[tid], m2 = sm[tid + off], s2 = ss[tid + off];
            float mm = fmaxf(m1, m2);
            ss[tid] = s1 * fast_exp_neg(m1 - mm) + s2 * fast_exp_neg(m2 - mm);
            sm[tid] = mm;
        }
        __syncthreads();
    }
    if (tid == 0) lse[row] = sm[0] + logf(ss[0]);
}

__global__ void sub_kernel(float* __restrict__ out, const float* __restrict__ lse) {
    int idx4 = blockIdx.x * 256 + threadIdx.x;   // ROWS*(VOC/4)
    int row = idx4 / (VOC / 4);
    float l = lse[row];
    float4* p = reinterpret_cast<float4*>(out) + idx4;
    float4 v = *p;
    v.x -= l; v.y -= l; v.z -= l; v.w -= l;
    *p = v;
}

// ------------------------------- launcher ---------------------------------
extern "C" void kernel_launch(void* const* d_in, const int* in_sizes, int n_in,
                              void* d_out, int out_size) {
    (void)in_sizes; (void)n_in; (void)out_size;
    const void*  inp   = d_in[0];
    const float* emb   = (const float*)d_in[1];
    const float* W_ih1 = (const float*)d_in[2];
    const float* W_hh1 = (const float*)d_in[3];
    const float* b_ih1 = (const float*)d_in[4];
    const float* b_hh1 = (const float*)d_in[5];
    const float* W_ih2 = (const float*)d_in[6];
    const float* W_hh2 = (const float*)d_in[7];
    const float* b_ih2 = (const float*)d_in[8];
    const float* b_hh2 = (const float*)d_in[9];
    const float* W_log = (const float*)d_in[10];
    const float* b_log = (const float*)d_in[11];
    float* out = (float*)d_out;

    static bool attr_set = false;
    if (!attr_set) {
        cudaFuncSetAttribute(lstm_layer, cudaFuncAttributeMaxDynamicSharedMemorySize, CELL_SMEM);
        attr_set = true;
    }

    float *X, *A, *h1s, *h2s, *h, *lse, *bias;
    cudaGetSymbolAddress((void**)&X,    g_X);
    cudaGetSymbolAddress((void**)&A,    g_A);
    cudaGetSymbolAddress((void**)&h1s,  g_h1seq);
    cudaGetSymbolAddress((void**)&h2s,  g_h2seq);
    cudaGetSymbolAddress((void**)&h,    g_h);
    cudaGetSymbolAddress((void**)&lse,  g_lse);
    cudaGetSymbolAddress((void**)&bias, g_bias);

    detect_i64<<<1, 256>>>((const unsigned int*)inp);
    combine_bias<<<16, 256>>>(b_ih1, b_hh1, b_ih2, b_hh2);
    gather_x<<<2048, 256>>>(inp, emb);

    // A1 = X @ W_ih1^T + (b_ih1 + b_hh1)
    gemm_nt<<<dim3(32, 32), 256>>>(X, W_ih1, A, ROWS, G4, EMB, bias);

    // layer 1 recurrence (persistent, seq layout rows r = s*16+b)
    zero_k<<<64, 256>>>(h, BATCH * HID);
    lstm_layer<<<NCTA, 256, CELL_SMEM>>>(A, W_hh1, h, h1s, 16 * HID, HID);

    // A2 = H1 @ W_ih2^T + (b_ih2 + b_hh2)
    gemm_nt<<<dim3(32, 32), 256>>>(h1s, W_ih2, A, ROWS, G4, HID, bias + G4);

    // layer 2 recurrence (persistent, writes [B,S,H] layout)
    zero_k<<<64, 256>>>(h, BATCH * HID);
    lstm_layer<<<NCTA, 256, CELL_SMEM>>>(A, W_hh2, h, h2s, HID, SEQ * HID);

    // logits = H2 @ W_log^T + b_log
    gemm_nt<<<dim3(250, 32), 256>>>(h2s, W_log, out, ROWS, VOC, HID, b_log);

    // log_softmax
    lse_kernel<<<ROWS, 256>>>(out, lse);
    sub_kernel<<<ROWS * (VOC / 4) / 256, 256>>>(out, lse);
}

// round 14
// speedup vs baseline: 1.1626x; 1.0157x over previous
#include <cuda_runtime.h>
#include <cuda_bf16.h>
#include <cfloat>
#include <math.h>

#define VOC   32000
#define EMB   512
#define HID   1024
#define BATCH 16
#define SEQ   256
#define G4    4096
#define ROWS  4096   // B*S
#define NCTA  128

// ------------------------------- device scratch ---------------------------
__device__ float g_X[ROWS * EMB];
__device__ float g_A[ROWS * G4];
__device__ float g_h1seq[ROWS * HID];   // rows r = s*16+b
__device__ float g_h2seq[ROWS * HID];   // rows r = b*256+s
__device__ float g_h[2 * BATCH * HID];
__device__ float g_lse[ROWS];
__device__ float g_bias[2 * G4];
__device__ int   g_is64;
__device__ unsigned g_cnt1[8 * 32];     // 8 group counters, 128B-line padded
__device__ unsigned g_cnt2;
__device__ unsigned g_gen;

// ------------------------------- f32x2 helpers -----------------------------
__device__ __forceinline__ void ffma2(unsigned long long& d,
                                      unsigned long long a,
                                      unsigned long long b) {
    asm("fma.rn.f32x2 %0, %1, %2, %0;" : "+l"(d) : "l"(a), "l"(b));
}
__device__ __forceinline__ unsigned long long pack2(float x, float y) {
    unsigned long long d;
    asm("mov.b64 %0, {%1, %2};" : "=l"(d) : "f"(x), "f"(y));
    return d;
}
__device__ __forceinline__ float2 unpack2(unsigned long long d) {
    float2 r;
    asm("mov.b64 {%0, %1}, %2;" : "=f"(r.x), "=f"(r.y) : "l"(d));
    return r;
}

// ------------------------------- small kernels ----------------------------
__global__ void zero_k(float* p, int n) {
    int i = blockIdx.x * 256 + threadIdx.x;
    if (i < n) p[i] = 0.f;
}

__global__ void reset_barrier() {
    int i = threadIdx.x;
    if (i < 8 * 32) g_cnt1[i] = 0u;
    if (i == 256) g_cnt2 = 0u;
    if (i == 257) g_gen = 0u;
}

__global__ void detect_i64(const unsigned int* p) {
    __shared__ int any;
    if (threadIdx.x == 0) any = 0;
    __syncthreads();
    int loc = 0;
    for (int i = threadIdx.x; i < 2048; i += 256) loc |= (p[2 * i + 1] != 0u);
    if (loc) atomicOr(&any, 1);
    __syncthreads();
    if (threadIdx.x == 0) g_is64 = (any == 0) ? 1 : 0;
}

__global__ void combine_bias(const float* __restrict__ a1, const float* __restrict__ a2,
                             const float* __restrict__ b1, const float* __restrict__ b2) {
    int i = blockIdx.x * 256 + threadIdx.x;
    if (i < G4) { g_bias[i] = a1[i] + a2[i]; g_bias[G4 + i] = b1[i] + b2[i]; }
}

__global__ void gather_x(const void* __restrict__ inp, const float* __restrict__ emb) {
    int idx4 = blockIdx.x * 256 + threadIdx.x;        // ROWS*128
    if (idx4 >= ROWS * (EMB / 4)) return;
    int r = idx4 >> 7, e4 = idx4 & 127;
    int s = r >> 4, b = r & 15;
    int pos = b * SEQ + s;
    int tok = g_is64 ? (int)((const long long*)inp)[pos] : ((const int*)inp)[pos];
    reinterpret_cast<float4*>(g_X)[idx4] =
        reinterpret_cast<const float4*>(emb)[(size_t)tok * 128 + e4];
}

// ------------------------------- SGEMM NT (f32x2, pipelined) ---------------
__global__ void __launch_bounds__(256, 2) gemm_nt(
    const float* __restrict__ A, const float* __restrict__ B, float* __restrict__ C,
    int M, int N, int K, const float* __restrict__ bias)
{
    __shared__ __align__(16) float As[16][132];
    __shared__ __align__(16) float Bs[16][132];
    const int tid = threadIdx.x;
    const int n0 = blockIdx.x * 128, m0 = blockIdx.y * 128;
    const int tx = tid & 15, ty = tid >> 4;
    const int lr = tid >> 1, lk = (tid & 1) * 8;

    unsigned long long acc2[8][4];
#pragma unroll
    for (int i = 0; i < 8; i++)
#pragma unroll
        for (int j = 0; j < 4; j++) acc2[i][j] = 0ull;

    const float* Ap = A + (size_t)(m0 + lr) * K + lk;
    const float* Bp = B + (size_t)(n0 + lr) * K + lk;

    float4 a0 = *reinterpret_cast<const float4*>(Ap);
    float4 a1 = *reinterpret_cast<const float4*>(Ap + 4);
    float4 b0 = *reinterpret_cast<const float4*>(Bp);
    float4 b1 = *reinterpret_cast<const float4*>(Bp + 4);
    As[lk+0][lr]=a0.x; As[lk+1][lr]=a0.y; As[lk+2][lr]=a0.z; As[lk+3][lr]=a0.w;
    As[lk+4][lr]=a1.x; As[lk+5][lr]=a1.y; As[lk+6][lr]=a1.z; As[lk+7][lr]=a1.w;
    Bs[lk+0][lr]=b0.x; Bs[lk+1][lr]=b0.y; Bs[lk+2][lr]=b0.z; Bs[lk+3][lr]=b0.w;
    Bs[lk+4][lr]=b1.x; Bs[lk+5][lr]=b1.y; Bs[lk+6][lr]=b1.z; Bs[lk+7][lr]=b1.w;
    __syncthreads();

    for (int k0 = 16; k0 <= K; k0 += 16) {
        bool more = (k0 < K);
        if (more) {
            a0 = *reinterpret_cast<const float4*>(Ap + k0);
            a1 = *reinterpret_cast<const float4*>(Ap + k0 + 4);
            b0 = *reinterpret_cast<const float4*>(Bp + k0);
            b1 = *reinterpret_cast<const float4*>(Bp + k0 + 4);
        }
#pragma unroll
        for (int kk = 0; kk < 16; ++kk) {
            float4 t0 = *reinterpret_cast<const float4*>(&As[kk][ty * 4]);
            float4 t1 = *reinterpret_cast<const float4*>(&As[kk][64 + ty * 4]);
            ulonglong2 u0 = *reinterpret_cast<const ulonglong2*>(&Bs[kk][tx * 4]);
            ulonglong2 u1 = *reinterpret_cast<const ulonglong2*>(&Bs[kk][64 + tx * 4]);
            unsigned long long bp[4] = { u0.x, u0.y, u1.x, u1.y };
            float a[8] = { t0.x,t0.y,t0.z,t0.w, t1.x,t1.y,t1.z,t1.w };
#pragma unroll
            for (int i = 0; i < 8; i++) {
                unsigned long long ai = pack2(a[i], a[i]);
#pragma unroll
                for (int j = 0; j < 4; j++) ffma2(acc2[i][j], ai, bp[j]);
            }
        }
        if (more) {
            __syncthreads();
            As[lk+0][lr]=a0.x; As[lk+1][lr]=a0.y; As[lk+2][lr]=a0.z; As[lk+3][lr]=a0.w;
            As[lk+4][lr]=a1.x; As[lk+5][lr]=a1.y; As[lk+6][lr]=a1.z; As[lk+7][lr]=a1.w;
            Bs[lk+0][lr]=b0.x; Bs[lk+1][lr]=b0.y; Bs[lk+2][lr]=b0.z; Bs[lk+3][lr]=b0.w;
            Bs[lk+4][lr]=b1.x; Bs[lk+5][lr]=b1.y; Bs[lk+6][lr]=b1.z; Bs[lk+7][lr]=b1.w;
            __syncthreads();
        }
    }

    float bn[8];
#pragma unroll
    for (int j = 0; j < 8; j++)
        bn[j] = bias ? bias[n0 + (j >> 2) * 64 + tx * 4 + (j & 3)] : 0.f;
#pragma unroll
    for (int i = 0; i < 8; i++) {
        int m = m0 + (i >> 2) * 64 + ty * 4 + (i & 3);
        float2 p0 = unpack2(acc2[i][0]), p1 = unpack2(acc2[i][1]);
        float2 p2 = unpack2(acc2[i][2]), p3 = unpack2(acc2[i][3]);
        float4 v0 = make_float4(p0.x+bn[0], p0.y+bn[1], p1.x+bn[2], p1.y+bn[3]);
        float4 v1 = make_float4(p2.x+bn[4], p2.y+bn[5], p3.x+bn[6], p3.y+bn[7]);
        *reinterpret_cast<float4*>(&C[(size_t)m * N + n0 + tx * 4]) = v0;
        *reinterpret_cast<float4*>(&C[(size_t)m * N + n0 + 64 + tx * 4]) = v1;
    }
}

// ------------------------------- barrier helper ----------------------------
__device__ __forceinline__ unsigned ld_acq(const unsigned* p) {
    unsigned v;
    asm volatile("ld.global.acquire.gpu.u32 %0, [%1];" : "=r"(v) : "l"(p));
    return v;
}

// ------------------------------- persistent LSTM layer --------------------
// 128 CTAs (one wave), each owns 8 hidden units for all 256 steps.
// red stride 17 (bank-conflict-free); fused reduce+pointwise; 2-level barrier.
#define H_STRIDE 1028
#define RED_STRIDE 17
#define CELL_SMEM ((16 * H_STRIDE + 256 * RED_STRIDE + 128) * 4)

__global__ void __launch_bounds__(256) lstm_layer(
    const float* __restrict__ pregA, const float* __restrict__ Whh,
    float* __restrict__ hbuf, float* __restrict__ seq_out,
    int stride_s, int stride_b)
{
    extern __shared__ float smem[];
    float* h_sm = smem;                        // 16 * H_STRIDE
    float* red  = smem + 16 * H_STRIDE;        // 256 * RED_STRIDE
    float* c_sm = red + 256 * RED_STRIDE;      // 128

    const int tid = threadIdx.x, cta = blockIdx.x;
    const int grp = cta >> 4;                  // 8 groups of 16 CTAs
    if (tid < 128) c_sm[tid] = 0.f;

    const int ks = tid >> 5, lane = tid & 31;
    const int rg = lane >> 2, bg = lane & 3;
    const int gate = rg >> 1, jl0 = (rg & 1) * 4;
    const int grow0 = gate * HID + cta * 8 + jl0;

    const ulonglong2* wpp[4];
#pragma unroll
    for (int r = 0; r < 4; r++)
        wpp[r] = reinterpret_cast<const ulonglong2*>(
            Whh + (size_t)(grow0 + r) * HID + ks * 128);

    // fused reduce+pointwise geometry (tid < 128)
    const int jl = tid & 7, b = tid >> 3;
    const int q_rd = (jl & 3) * 4 + (b >> 2);
    int src_rd[4];
#pragma unroll
    for (int g = 0; g < 4; g++)
        src_rd[g] = (g * 2 + (jl >> 2)) * 4 + (b & 3);

    for (int s = 0; s < SEQ; s++) {
        const float* h_in  = hbuf + (s & 1) * (BATCH * HID);
        float*       h_out = hbuf + ((s + 1) & 1) * (BATCH * HID);
        const float* preg  = pregA + (size_t)s * 16 * G4;

        // prefetch this step's 4 gate pre-activations for (jl, b)
        float pv[4] = {0.f, 0.f, 0.f, 0.f};
        if (tid < 128) {
#pragma unroll
            for (int g = 0; g < 4; g++)
                pv[g] = __ldcg(&preg[(size_t)b * G4 + g * HID + cta * 8 + jl]);
        }

        // stage h (L2-coherent loads)
        for (int t = tid; t < BATCH * (HID / 4); t += 256) {
            int bb = t >> 8, k4 = t & 255;
            float4 v = __ldcg(reinterpret_cast<const float4*>(h_in) + bb * 256 + k4);
            *reinterpret_cast<float4*>(&h_sm[bb * H_STRIDE + k4 * 4]) = v;
        }
        __syncthreads();

        const ulonglong2* hq[4];
#pragma unroll
        for (int q = 0; q < 4; q++)
            hq[q] = reinterpret_cast<const ulonglong2*>(
                &h_sm[(bg + 4 * q) * H_STRIDE + ks * 128]);

        unsigned long long acc2[16];
#pragma unroll
        for (int q = 0; q < 16; q++) acc2[q] = 0ull;

#pragma unroll 4
        for (int kk = 0; kk < 32; kk++) {   // 32 x (4 k-values)
            ulonglong2 wv[4], hv[4];
#pragma unroll
            for (int r = 0; r < 4; r++) wv[r] = wpp[r][kk];
#pragma unroll
            for (int q = 0; q < 4; q++) hv[q] = hq[q][kk];
#pragma unroll
            for (int r = 0; r < 4; r++)
#pragma unroll
                for (int q = 0; q < 4; q++) {
                    ffma2(acc2[r * 4 + q], wv[r].x, hv[q].x);
                    ffma2(acc2[r * 4 + q], wv[r].y, hv[q].y);
                }
        }

#pragma unroll
        for (int q = 0; q < 16; q++) {
            float2 p = unpack2(acc2[q]);
            red[tid * RED_STRIDE + q] = p.x + p.y;   // stride 17: conflict-free
        }
        __syncthreads();

        if (tid < 128) {
            float gv4[4];
#pragma unroll
            for (int g = 0; g < 4; g++) {
                float sum = pv[g];
#pragma unroll
                for (int p = 0; p < 8; p++)
                    sum += red[(p * 32 + src_rd[g]) * RED_STRIDE + q_rd];
                gv4[g] = sum;
            }
            float si = 1.f / (1.f + expf(-gv4[0]));
            float sf = 1.f / (1.f + expf(-gv4[1]));
            float so = 1.f / (1.f + expf(-gv4[3]));
            float cn = sf * c_sm[tid] + si * tanhf(gv4[2]);
            float hn = so * tanhf(cn);
            c_sm[tid] = cn;
            h_out[b * HID + cta * 8 + jl] = hn;
            seq_out[(size_t)s * stride_s + (size_t)b * stride_b + cta * 8 + jl] = hn;
        }

        // two-level grid barrier (skip after last step)
        if (s == SEQ - 1) break;
        __syncthreads();
        if (tid == 0) {
            __threadfence();
            unsigned v = atomicAdd(&g_cnt1[grp * 32], 1u) + 1u;
            if (v == (unsigned)(16 * (s + 1))) {
                unsigned r = atomicAdd(&g_cnt2, 1u) + 1u;
                if (r == (unsigned)(8 * (s + 1)))
                    atomicAdd(&g_gen, 1u);
            }
            unsigned tgt = (unsigned)(s + 1);
            while (ld_acq(&g_gen) < tgt) __nanosleep(16);
        }
        __syncthreads();
    }
}

// ------------------------------- log-softmax (fused) ----------------------
__device__ __forceinline__ float fast_exp_neg(float x) {   // x <= 0
    x = fmaxf(x, -87.0f);
    float t = x * 1.4426950408889634f;
    float fl = floorf(t);
    float r = t - fl;
    float p = 1.5403530393381609e-4f;
    p = fmaf(p, r, 1.3333558146428443e-3f);
    p = fmaf(p, r, 9.6181291076284772e-3f);
    p = fmaf(p, r, 5.5504108664821580e-2f);
    p = fmaf(p, r, 2.4022650695910072e-1f);
    p = fmaf(p, r, 6.9314718055994531e-1f);
    p = fmaf(p, r, 1.0f);
    return p * __int_as_float(((int)fl + 127) << 23);
}

__global__ void logsoftmax_kernel(float* __restrict__ out) {
    __shared__ float sm[256], ss[256];
    const int row = blockIdx.x, tid = threadIdx.x;
    float4* base = reinterpret_cast<float4*>(out + (size_t)row * VOC);
    float m = -FLT_MAX, s = 0.f;
    for (int i = tid; i < VOC / 4; i += 256) {
        float4 v = base[i];
        float xs[4] = { v.x, v.y, v.z, v.w };
#pragma unroll
        for (int q = 0; q < 4; q++) {
            float x = xs[q];
            if (x > m) { s = s * fast_exp_neg(m - x) + 1.f; m = x; }
            else       { s += fast_exp_neg(x - m); }
        }
    }
    sm[tid] = m; ss[tid] = s;
    __syncthreads();
    for (int off = 128; off; off >>= 1) {
        if (tid < off) {
            float m1 = sm[tid], s1 = ss[tid], m2 = sm[tid + off], s2 = ss[tid + off];
            float mm = fmaxf(m1, m2);
            ss[tid] = s1 * fast_exp_neg(m1 - mm) + s2 * fast_exp_neg(m2 - mm);
            sm[tid] = mm;
        }
        __syncthreads();
    }
    float l = sm[0] + logf(ss[0]);
    // subtract in the same kernel (row is L2-hot)
    for (int i = tid; i < VOC / 4; i += 256) {
        float4 v = base[i];
        v.x -= l; v.y -= l; v.z -= l; v.w -= l;
        base[i] = v;
    }
}

// ------------------------------- launcher ---------------------------------
extern "C" void kernel_launch(void* const* d_in, const int* in_sizes, int n_in,
                              void* d_out, int out_size) {
    (void)in_sizes; (void)n_in; (void)out_size;
    const void*  inp   = d_in[0];
    const float* emb   = (const float*)d_in[1];
    const float* W_ih1 = (const float*)d_in[2];
    const float* W_hh1 = (const float*)d_in[3];
    const float* b_ih1 = (const float*)d_in[4];
    const float* b_hh1 = (const float*)d_in[5];
    const float* W_ih2 = (const float*)d_in[6];
    const float* W_hh2 = (const float*)d_in[7];
    const float* b_ih2 = (const float*)d_in[8];
    const float* b_hh2 = (const float*)d_in[9];
    const float* W_log = (const float*)d_in[10];
    const float* b_log = (const float*)d_in[11];
    float* out = (float*)d_out;

    static bool attr_set = false;
    if (!attr_set) {
        cudaFuncSetAttribute(lstm_layer, cudaFuncAttributeMaxDynamicSharedMemorySize, CELL_SMEM);
        attr_set = true;
    }

    float *X, *A, *h1s, *h2s, *h, *bias;
    cudaGetSymbolAddress((void**)&X,    g_X);
    cudaGetSymbolAddress((void**)&A,    g_A);
    cudaGetSymbolAddress((void**)&h1s,  g_h1seq);
    cudaGetSymbolAddress((void**)&h2s,  g_h2seq);
    cudaGetSymbolAddress((void**)&h,    g_h);
    cudaGetSymbolAddress((void**)&bias, g_bias);

    detect_i64<<<1, 256>>>((const unsigned int*)inp);
    combine_bias<<<16, 256>>>(b_ih1, b_hh1, b_ih2, b_hh2);
    gather_x<<<2048, 256>>>(inp, emb);

    // A1 = X @ W_ih1^T + (b_ih1 + b_hh1)
    gemm_nt<<<dim3(32, 32), 256>>>(X, W_ih1, A, ROWS, G4, EMB, bias);

    // layer 1 recurrence (persistent, seq layout rows r = s*16+b)
    zero_k<<<64, 256>>>(h, BATCH * HID);
    reset_barrier<<<1, 288>>>();
    lstm_layer<<<NCTA, 256, CELL_SMEM>>>(A, W_hh1, h, h1s, 16 * HID, HID);

    // A2 = H1 @ W_ih2^T + (b_ih2 + b_hh2)
    gemm_nt<<<dim3(32, 32), 256>>>(h1s, W_ih2, A, ROWS, G4, HID, bias + G4);

    // layer 2 recurrence (persistent, writes [B,S,H] layout)
    zero_k<<<64, 256>>>(h, BATCH * HID);
    reset_barrier<<<1, 288>>>();
    lstm_layer<<<NCTA, 256, CELL_SMEM>>>(A, W_hh2, h, h2s, HID, SEQ * HID);

    // logits = H2 @ W_log^T + b_log
    gemm_nt<<<dim3(250, 32), 256>>>(h2s, W_log, out, ROWS, VOC, HID, b_log);

    // fused log_softmax (in-place)
    logsoftmax_kernel<<<ROWS, 256>>>(out);
}

// round 16
// speedup vs baseline: 1.3868x; 1.1929x over previous
#include <cuda_runtime.h>
#include <cuda_bf16.h>
#include <cfloat>
#include <math.h>

#define VOC   32000
#define EMB   512
#define HID   1024
#define BATCH 16
#define SEQ   256
#define G4    4096
#define ROWS  4096   // B*S
#define NCTA  128

// ------------------------------- device scratch ---------------------------
__device__ float g_X[ROWS * EMB];
__device__ float g_A[ROWS * G4];
__device__ float g_h1seq[ROWS * HID];   // rows r = s*16+b
__device__ float g_h2seq[ROWS * HID];   // rows r = b*256+s
__device__ float g_hT[2 * HID * BATCH]; // transposed [k][b] ping-pong
__device__ float g_bias[2 * G4];
__device__ int   g_is64;
__device__ unsigned g_cnt1[8 * 32];     // 8 group counters, 128B-line padded
__device__ unsigned g_cnt2;
__device__ unsigned g_gen;

// ------------------------------- f32x2 helpers -----------------------------
__device__ __forceinline__ void ffma2(unsigned long long& d,
                                      unsigned long long a,
                                      unsigned long long b) {
    asm("fma.rn.f32x2 %0, %1, %2, %0;" : "+l"(d) : "l"(a), "l"(b));
}
__device__ __forceinline__ void fadd2(unsigned long long& d,
                                      unsigned long long a) {
    asm("add.rn.f32x2 %0, %0, %1;" : "+l"(d) : "l"(a));
}
__device__ __forceinline__ unsigned long long pack2(float x, float y) {
    unsigned long long d;
    asm("mov.b64 %0, {%1, %2};" : "=l"(d) : "f"(x), "f"(y));
    return d;
}
__device__ __forceinline__ float2 unpack2(unsigned long long d) {
    float2 r;
    asm("mov.b64 {%0, %1}, %2;" : "=f"(r.x), "=f"(r.y) : "l"(d));
    return r;
}

// ------------------------------- small kernels ----------------------------
__global__ void zero_k(float* p, int n) {
    int i = blockIdx.x * 256 + threadIdx.x;
    if (i < n) p[i] = 0.f;
}

__global__ void reset_barrier() {
    int i = threadIdx.x;
    if (i < 8 * 32) g_cnt1[i] = 0u;
    if (i == 256) g_cnt2 = 0u;
    if (i == 257) g_gen = 0u;
}

__global__ void detect_i64(const unsigned int* p) {
    __shared__ int any;
    if (threadIdx.x == 0) any = 0;
    __syncthreads();
    int loc = 0;
    for (int i = threadIdx.x; i < 2048; i += 256) loc |= (p[2 * i + 1] != 0u);
    if (loc) atomicOr(&any, 1);
    __syncthreads();
    if (threadIdx.x == 0) g_is64 = (any == 0) ? 1 : 0;
}

__global__ void combine_bias(const float* __restrict__ a1, const float* __restrict__ a2,
                             const float* __restrict__ b1, const float* __restrict__ b2) {
    int i = blockIdx.x * 256 + threadIdx.x;
    if (i < G4) { g_bias[i] = a1[i] + a2[i]; g_bias[G4 + i] = b1[i] + b2[i]; }
}

__global__ void gather_x(const void* __restrict__ inp, const float* __restrict__ emb) {
    int idx4 = blockIdx.x * 256 + threadIdx.x;        // ROWS*128
    if (idx4 >= ROWS * (EMB / 4)) return;
    int r = idx4 >> 7, e4 = idx4 & 127;
    int s = r >> 4, b = r & 15;
    int pos = b * SEQ + s;
    int tok = g_is64 ? (int)((const long long*)inp)[pos] : ((const int*)inp)[pos];
    reinterpret_cast<float4*>(g_X)[idx4] =
        reinterpret_cast<const float4*>(emb)[(size_t)tok * 128 + e4];
}

// ------------------------------- SGEMM NT (f32x2, pipelined) ---------------
__global__ void __launch_bounds__(256, 2) gemm_nt(
    const float* __restrict__ A, const float* __restrict__ B, float* __restrict__ C,
    int M, int N, int K, const float* __restrict__ bias)
{
    __shared__ __align__(16) float As[16][132];
    __shared__ __align__(16) float Bs[16][132];
    const int tid = threadIdx.x;
    const int n0 = blockIdx.x * 128, m0 = blockIdx.y * 128;
    const int tx = tid & 15, ty = tid >> 4;
    const int lr = tid >> 1, lk = (tid & 1) * 8;

    unsigned long long acc2[8][4];
#pragma unroll
    for (int i = 0; i < 8; i++)
#pragma unroll
        for (int j = 0; j < 4; j++) acc2[i][j] = 0ull;

    const float* Ap = A + (size_t)(m0 + lr) * K + lk;
    const float* Bp = B + (size_t)(n0 + lr) * K + lk;

    float4 a0 = *reinterpret_cast<const float4*>(Ap);
    float4 a1 = *reinterpret_cast<const float4*>(Ap + 4);
    float4 b0 = *reinterpret_cast<const float4*>(Bp);
    float4 b1 = *reinterpret_cast<const float4*>(Bp + 4);
    As[lk+0][lr]=a0.x; As[lk+1][lr]=a0.y; As[lk+2][lr]=a0.z; As[lk+3][lr]=a0.w;
    As[lk+4][lr]=a1.x; As[lk+5][lr]=a1.y; As[lk+6][lr]=a1.z; As[lk+7][lr]=a1.w;
    Bs[lk+0][lr]=b0.x; Bs[lk+1][lr]=b0.y; Bs[lk+2][lr]=b0.z; Bs[lk+3][lr]=b0.w;
    Bs[lk+4][lr]=b1.x; Bs[lk+5][lr]=b1.y; Bs[lk+6][lr]=b1.z; Bs[lk+7][lr]=b1.w;
    __syncthreads();

    for (int k0 = 16; k0 <= K; k0 += 16) {
        bool more = (k0 < K);
        if (more) {
            a0 = *reinterpret_cast<const float4*>(Ap + k0);
            a1 = *reinterpret_cast<const float4*>(Ap + k0 + 4);
            b0 = *reinterpret_cast<const float4*>(Bp + k0);
            b1 = *reinterpret_cast<const float4*>(Bp + k0 + 4);
        }
#pragma unroll
        for (int kk = 0; kk < 16; ++kk) {
            float4 t0 = *reinterpret_cast<const float4*>(&As[kk][ty * 4]);
            float4 t1 = *reinterpret_cast<const float4*>(&As[kk][64 + ty * 4]);
            ulonglong2 u0 = *reinterpret_cast<const ulonglong2*>(&Bs[kk][tx * 4]);
            ulonglong2 u1 = *reinterpret_cast<const ulonglong2*>(&Bs[kk][64 + tx * 4]);
            unsigned long long bp[4] = { u0.x, u0.y, u1.x, u1.y };
            float a[8] = { t0.x,t0.y,t0.z,t0.w, t1.x,t1.y,t1.z,t1.w };
#pragma unroll
            for (int i = 0; i < 8; i++) {
                unsigned long long ai = pack2(a[i], a[i]);
#pragma unroll
                for (int j = 0; j < 4; j++) ffma2(acc2[i][j], ai, bp[j]);
            }
        }
        if (more) {
            __syncthreads();
            As[lk+0][lr]=a0.x; As[lk+1][lr]=a0.y; As[lk+2][lr]=a0.z; As[lk+3][lr]=a0.w;
            As[lk+4][lr]=a1.x; As[lk+5][lr]=a1.y; As[lk+6][lr]=a1.z; As[lk+7][lr]=a1.w;
            Bs[lk+0][lr]=b0.x; Bs[lk+1][lr]=b0.y; Bs[lk+2][lr]=b0.z; Bs[lk+3][lr]=b0.w;
            Bs[lk+4][lr]=b1.x; Bs[lk+5][lr]=b1.y; Bs[lk+6][lr]=b1.z; Bs[lk+7][lr]=b1.w;
            __syncthreads();
        }
    }

    float bn[8];
#pragma unroll
    for (int j = 0; j < 8; j++)
        bn[j] = bias ? bias[n0 + (j >> 2) * 64 + tx * 4 + (j & 3)] : 0.f;
#pragma unroll
    for (int i = 0; i < 8; i++) {
        int m = m0 + (i >> 2) * 64 + ty * 4 + (i & 3);
        float2 p0 = unpack2(acc2[i][0]), p1 = unpack2(acc2[i][1]);
        float2 p2 = unpack2(acc2[i][2]), p3 = unpack2(acc2[i][3]);
        float4 v0 = make_float4(p0.x+bn[0], p0.y+bn[1], p1.x+bn[2], p1.y+bn[3]);
        float4 v1 = make_float4(p2.x+bn[4], p2.y+bn[5], p3.x+bn[6], p3.y+bn[7]);
        *reinterpret_cast<float4*>(&C[(size_t)m * N + n0 + tx * 4]) = v0;
        *reinterpret_cast<float4*>(&C[(size_t)m * N + n0 + 64 + tx * 4]) = v1;
    }
}

// ------------------------------- barrier helper ----------------------------
__device__ __forceinline__ unsigned ld_acq(const unsigned* p) {
    unsigned v;
    asm volatile("ld.global.acquire.gpu.u32 %0, [%1];" : "=r"(v) : "l"(p));
    return v;
}

// ------------------------------- persistent LSTM layer --------------------
// 128 CTAs, 1/SM. Each thread holds 1 gate row x 128-k weight slice in
// REGISTERS for all 256 steps. h is transposed [k][b]; each h operand is a
// broadcast LDS.128 across the warp. FFMA2 packs batch pairs.
// smem: h_sm 16384 f | red 2560 ull (stride 10 -> 16B-aligned ulonglong2)
//       | g_sm 544 f | c_sm 128 f
#define SM_H    16384
#define SM_RED  (SM_H)               // float offset of red region
#define SM_G    (SM_H + 5120)        // 2560 ull = 5120 floats
#define SM_C    (SM_G + 544)
#define CELL_SMEM ((SM_C + 128) * 4)

__global__ void __launch_bounds__(256, 1) lstm_layer(
    const float* __restrict__ pregA, const float* __restrict__ Whh,
    float* __restrict__ hbufT, float* __restrict__ seq_out,
    int stride_s, int stride_b)
{
    extern __shared__ float smem[];
    float* h_sm = smem;
    unsigned long long* red = reinterpret_cast<unsigned long long*>(smem + SM_RED);
    float* g_sm = smem + SM_G;
    float* c_sm = smem + SM_C;

    const int tid = threadIdx.x, cta = blockIdx.x;
    const int grp = cta >> 4;
    const int wid = tid >> 5, lane = tid & 31;        // wid = k-slice
    if (tid < 128) c_sm[tid] = 0.f;

    // weight slice -> registers: row (lane) = gate*8+jl, k in [wid*128, +128)
    const int row_g = (lane >> 3) * HID + cta * 8 + (lane & 7);
    float wr[128];
    {
        const float4* wp = reinterpret_cast<const float4*>(
            Whh + (size_t)row_g * HID + wid * 128);
#pragma unroll
        for (int i = 0; i < 32; i++) {
            float4 v = __ldg(wp + i);
            wr[4*i+0] = v.x; wr[4*i+1] = v.y; wr[4*i+2] = v.z; wr[4*i+3] = v.w;
        }
    }

    // reduce geometry: thread -> (row 0..31, batch-pair 0..7)
    const int r_row = tid >> 3, r_bp = tid & 7;
    // pointwise geometry (tid < 128)
    const int jl = tid & 7, b = tid >> 3;

    for (int s = 0; s < SEQ; s++) {
        const float* hin  = hbufT + (s & 1) * (HID * BATCH);
        float*       hout = hbufT + ((s + 1) & 1) * (HID * BATCH);
        const float* preg = pregA + (size_t)s * 16 * G4;

        float pv[4] = {0.f, 0.f, 0.f, 0.f};
        if (tid < 128) {
#pragma unroll
            for (int g = 0; g < 4; g++)
                pv[g] = __ldcg(&preg[(size_t)b * G4 + g * HID + cta * 8 + jl]);
        }

        // stage h: straight 64 KB copy (layout [k][b] matches smem)
#pragma unroll
        for (int t = 0; t < 16; t++) {
            int idx = tid + t * 256;
            float4 v = __ldcg(reinterpret_cast<const float4*>(hin) + idx);
            *reinterpret_cast<float4*>(&h_sm[idx * 4]) = v;
        }
        __syncthreads();

        // FMA phase: per k: 4 broadcast LDS.128 + 1 splat + 8 FFMA2
        unsigned long long acc2[8];
#pragma unroll
        for (int p = 0; p < 8; p++) acc2[p] = 0ull;
        const ulonglong2* hbase = reinterpret_cast<const ulonglong2*>(
            h_sm + wid * 128 * BATCH);
#pragma unroll
        for (int k = 0; k < 128; k++) {
            ulonglong2 h01 = hbase[k * 4 + 0];
            ulonglong2 h23 = hbase[k * 4 + 1];
            ulonglong2 h45 = hbase[k * 4 + 2];
            ulonglong2 h67 = hbase[k * 4 + 3];
            unsigned long long ws = pack2(wr[k], wr[k]);
            ffma2(acc2[0], ws, h01.x); ffma2(acc2[1], ws, h01.y);
            ffma2(acc2[2], ws, h23.x); ffma2(acc2[3], ws, h23.y);
            ffma2(acc2[4], ws, h45.x); ffma2(acc2[5], ws, h45.y);
            ffma2(acc2[6], ws, h67.x); ffma2(acc2[7], ws, h67.y);
        }

        // partials to smem (stride 10 ull = 80 B: ulonglong2 stays 16B-aligned)
        {
            unsigned long long* rp = red + (size_t)tid * 10;
#pragma unroll
            for (int p = 0; p < 8; p += 2)
                *reinterpret_cast<ulonglong2*>(rp + p) =
                    make_ulonglong2(acc2[p], acc2[p + 1]);
        }
        __syncthreads();

        // reduce over 8 k-slices -> g_sm[row*17 + b]
        {
            unsigned long long s2 = 0ull;
#pragma unroll
            for (int ks = 0; ks < 8; ks++)
                fadd2(s2, red[(size_t)(ks * 32 + r_row) * 10 + r_bp]);
            float2 p = unpack2(s2);
            g_sm[r_row * 17 + r_bp * 2 + 0] = p.x;
            g_sm[r_row * 17 + r_bp * 2 + 1] = p.y;
        }
        __syncthreads();

        // pointwise + writes
        if (tid < 128) {
            float iv = pv[0] + g_sm[(0  + jl) * 17 + b];
            float fv = pv[1] + g_sm[(8  + jl) * 17 + b];
            float gv = pv[2] + g_sm[(16 + jl) * 17 + b];
            float ov = pv[3] + g_sm[(24 + jl) * 17 + b];
            float si = 1.f / (1.f + expf(-iv));
            float sf = 1.f / (1.f + expf(-fv));
            float so = 1.f / (1.f + expf(-ov));
            float cn = sf * c_sm[tid] + si * tanhf(gv);
            float hn = so * tanhf(cn);
            c_sm[tid] = cn;
            hout[(cta * 8 + jl) * BATCH + b] = hn;   // transposed [k][b]
            seq_out[(size_t)s * stride_s + (size_t)b * stride_b + cta * 8 + jl] = hn;
        }

        if (s == SEQ - 1) break;
        __syncthreads();
        if (tid == 0) {
            __threadfence();
            unsigned v = atomicAdd(&g_cnt1[grp * 32], 1u) + 1u;
            if (v == (unsigned)(16 * (s + 1))) {
                unsigned r = atomicAdd(&g_cnt2, 1u) + 1u;
                if (r == (unsigned)(8 * (s + 1)))
                    atomicAdd(&g_gen, 1u);
            }
            unsigned tgt = (unsigned)(s + 1);
            while (ld_acq(&g_gen) < tgt) __nanosleep(16);
        }
        __syncthreads();
    }
}

// ------------------------------- log-softmax (fused) ----------------------
__device__ __forceinline__ float fast_exp_neg(float x) {   // x <= 0
    x = fmaxf(x, -87.0f);
    float t = x * 1.4426950408889634f;
    float fl = floorf(t);
    float r = t - fl;
    float p = 1.5403530393381609e-4f;
    p = fmaf(p, r, 1.3333558146428443e-3f);
    p = fmaf(p, r, 9.6181291076284772e-3f);
    p = fmaf(p, r, 5.5504108664821580e-2f);
    p = fmaf(p, r, 2.4022650695910072e-1f);
    p = fmaf(p, r, 6.9314718055994531e-1f);
    p = fmaf(p, r, 1.0f);
    return p * __int_as_float(((int)fl + 127) << 23);
}

__global__ void logsoftmax_kernel(float* __restrict__ out) {
    __shared__ float sm[256], ss[256];
    const int row = blockIdx.x, tid = threadIdx.x;
    float4* base = reinterpret_cast<float4*>(out + (size_t)row * VOC);
    float m = -FLT_MAX, s = 0.f;
    for (int i = tid; i < VOC / 4; i += 256) {
        float4 v = base[i];
        float xs[4] = { v.x, v.y, v.z, v.w };
#pragma unroll
        for (int q = 0; q < 4; q++) {
            float x = xs[q];
            if (x > m) { s = s * fast_exp_neg(m - x) + 1.f; m = x; }
            else       { s += fast_exp_neg(x - m); }
        }
    }
    sm[tid] = m; ss[tid] = s;
    __syncthreads();
    for (int off = 128; off; off >>= 1) {
        if (tid < off) {
            float m1 = sm[tid], s1 = ss[tid], m2 = sm[tid + off], s2 = ss[tid + off];
            float mm = fmaxf(m1, m2);
            ss[tid] = s1 * fast_exp_neg(m1 - mm) + s2 * fast_exp_neg(m2 - mm);
            sm[tid] = mm;
        }
        __syncthreads();
    }
    float l = sm[0] + logf(ss[0]);
    for (int i = tid; i < VOC / 4; i += 256) {
        float4 v = base[i];
        v.x -= l; v.y -= l; v.z -= l; v.w -= l;
        base[i] = v;
    }
}

// ------------------------------- launcher ---------------------------------
extern "C" void kernel_launch(void* const* d_in, const int* in_sizes, int n_in,
                              void* d_out, int out_size) {
    (void)in_sizes; (void)n_in; (void)out_size;
    const void*  inp   = d_in[0];
    const float* emb   = (const float*)d_in[1];
    const float* W_ih1 = (const float*)d_in[2];
    const float* W_hh1 = (const float*)d_in[3];
    const float* b_ih1 = (const float*)d_in[4];
    const float* b_hh1 = (const float*)d_in[5];
    const float* W_ih2 = (const float*)d_in[6];
    const float* W_hh2 = (const float*)d_in[7];
    const float* b_ih2 = (const float*)d_in[8];
    const float* b_hh2 = (const float*)d_in[9];
    const float* W_log = (const float*)d_in[10];
    const float* b_log = (const float*)d_in[11];
    float* out = (float*)d_out;

    static bool attr_set = false;
    if (!attr_set) {
        cudaFuncSetAttribute(lstm_layer, cudaFuncAttributeMaxDynamicSharedMemorySize, CELL_SMEM);
        attr_set = true;
    }

    float *X, *A, *h1s, *h2s, *hT, *bias;
    cudaGetSymbolAddress((void**)&X,    g_X);
    cudaGetSymbolAddress((void**)&A,    g_A);
    cudaGetSymbolAddress((void**)&h1s,  g_h1seq);
    cudaGetSymbolAddress((void**)&h2s,  g_h2seq);
    cudaGetSymbolAddress((void**)&hT,   g_hT);
    cudaGetSymbolAddress((void**)&bias, g_bias);

    detect_i64<<<1, 256>>>((const unsigned int*)inp);
    combine_bias<<<16, 256>>>(b_ih1, b_hh1, b_ih2, b_hh2);
    gather_x<<<2048, 256>>>(inp, emb);

    // A1 = X @ W_ih1^T + (b_ih1 + b_hh1)
    gemm_nt<<<dim3(32, 32), 256>>>(X, W_ih1, A, ROWS, G4, EMB, bias);

    // layer 1 recurrence (persistent, seq layout rows r = s*16+b)
    zero_k<<<64, 256>>>(hT, HID * BATCH);
    reset_barrier<<<1, 288>>>();
    lstm_layer<<<NCTA, 256, CELL_SMEM>>>(A, W_hh1, hT, h1s, 16 * HID, HID);

    // A2 = H1 @ W_ih2^T + (b_ih2 + b_hh2)
    gemm_nt<<<dim3(32, 32), 256>>>(h1s, W_ih2, A, ROWS, G4, HID, bias + G4);

    // layer 2 recurrence (persistent, writes [B,S,H] layout)
    zero_k<<<64, 256>>>(hT, HID * BATCH);
    reset_barrier<<<1, 288>>>();
    lstm_layer<<<NCTA, 256, CELL_SMEM>>>(A, W_hh2, hT, h2s, HID, SEQ * HID);

    // logits = H2 @ W_log^T + b_log
    gemm_nt<<<dim3(250, 32), 256>>>(h2s, W_log, out, ROWS, VOC, HID, b_log);

    // fused log_softmax (in-place)
    logsoftmax_kernel<<<ROWS, 256>>>(out);
}